// round 16
// baseline (speedup 1.0000x reference)
#include <cuda_runtime.h>
#include <cuda_bf16.h>
#include <cstdint>
#include <math.h>

#define B_   2
#define N_   2048
#define D_   1024
#define H_   16
#define DK_  64
#define M_   (B_ * N_)   // 4096

#define QSCALE 0.1803368801111204f   // 0.125 * log2(e)
#define LOG2E  1.4426950408889634f

// ---------------- scratch (allocation-free rule: __device__ globals) -------
__device__ __nv_bfloat16 g_Ah[M_ * D_];     // x split, later Y split
__device__ __nv_bfloat16 g_Al[M_ * D_];
__device__ __nv_bfloat16 g_Wh[4][D_ * D_];  // transposed weights [n][k], hi
__device__ __nv_bfloat16 g_Wl[4][D_ * D_];  // lo
__device__ __nv_bfloat16 g_Qh[B_ * H_ * N_ * DK_];
__device__ __nv_bfloat16 g_Ql[B_ * H_ * N_ * DK_];
__device__ __nv_bfloat16 g_Kh[B_ * H_ * N_ * DK_];
__device__ __nv_bfloat16 g_Kl[B_ * H_ * N_ * DK_];
__device__ __nv_bfloat16 g_Vh[B_ * H_ * N_ * DK_];
__device__ __nv_bfloat16 g_Vl[B_ * H_ * N_ * DK_];

// ---------------- PTX helpers (baseline ISA: sm_80-level only) -------------
__device__ __forceinline__ uint32_t smem_u32(const void* p) {
    uint32_t a;
    asm("{ .reg .u64 t; cvta.to.shared.u64 t, %1; cvt.u32.u64 %0, t; }"
        : "=r"(a) : "l"(p));
    return a;
}
__device__ __forceinline__ void ldmx4(uint32_t& r0, uint32_t& r1,
                                      uint32_t& r2, uint32_t& r3, uint32_t a) {
    asm volatile("ldmatrix.sync.aligned.m8n8.x4.shared.b16 {%0,%1,%2,%3}, [%4];"
                 : "=r"(r0), "=r"(r1), "=r"(r2), "=r"(r3) : "r"(a));
}
__device__ __forceinline__ void ldmx4t(uint32_t& r0, uint32_t& r1,
                                       uint32_t& r2, uint32_t& r3, uint32_t a) {
    asm volatile("ldmatrix.sync.aligned.m8n8.x4.trans.shared.b16 {%0,%1,%2,%3}, [%4];"
                 : "=r"(r0), "=r"(r1), "=r"(r2), "=r"(r3) : "r"(a));
}
__device__ __forceinline__ void ldmx2(uint32_t& r0, uint32_t& r1, uint32_t a) {
    asm volatile("ldmatrix.sync.aligned.m8n8.x2.shared.b16 {%0,%1}, [%2];"
                 : "=r"(r0), "=r"(r1) : "r"(a));
}
__device__ __forceinline__ void mma16816(float* c, const uint32_t* a,
                                         const uint32_t* b) {
    asm volatile(
        "mma.sync.aligned.m16n8k16.row.col.f32.bf16.bf16.f32 "
        "{%0,%1,%2,%3}, {%4,%5,%6,%7}, {%8,%9}, {%0,%1,%2,%3};"
        : "+f"(c[0]), "+f"(c[1]), "+f"(c[2]), "+f"(c[3])
        : "r"(a[0]), "r"(a[1]), "r"(a[2]), "r"(a[3]), "r"(b[0]), "r"(b[1]));
}
__device__ __forceinline__ float ex2(float x) {
    float r;
    asm("ex2.approx.ftz.f32 %0, %1;" : "=f"(r) : "f"(x));
    return r;
}
__device__ __forceinline__ void split2(float x, float y, uint32_t& h, uint32_t& l) {
    __nv_bfloat16 hx = __float2bfloat16(x), hy = __float2bfloat16(y);
    __nv_bfloat16 lx = __float2bfloat16(x - __bfloat162float(hx));
    __nv_bfloat16 ly = __float2bfloat16(y - __bfloat162float(hy));
    __nv_bfloat162 hp(hx, hy), lp(lx, ly);
    h = *(uint32_t*)&hp; l = *(uint32_t*)&lp;
}
#define CP16(dst, src) \
    asm volatile("cp.async.ca.shared.global [%0], [%1], 16;" :: "r"(dst), "l"(src))
#define CPCOMMIT() asm volatile("cp.async.commit_group;" ::: "memory")
#define CPWAIT(n)  asm volatile("cp.async.wait_group %0;" :: "n"(n) : "memory")

// ---------------------------------------------------------------------------
// prep: grid (32,32,5). z<4: W[z] transpose+split. z==4: x elementwise split.
// ---------------------------------------------------------------------------
__global__ __launch_bounds__(256) void prep_kernel(
    const float* __restrict__ X,
    const float* __restrict__ W0, const float* __restrict__ W1,
    const float* __restrict__ W2, const float* __restrict__ W3,
    __nv_bfloat16* __restrict__ Th, __nv_bfloat16* __restrict__ Tl,
    __nv_bfloat16* __restrict__ Xh, __nv_bfloat16* __restrict__ Xl)
{
    __shared__ float t[32][33];
    const int z = blockIdx.z;
    if (z == 4) {
        int base = (blockIdx.x * 32 + blockIdx.y) * 256 + threadIdx.x;
        #pragma unroll
        for (int tt = 0; tt < 4; ++tt) {
            int i = base + tt * 262144;
            float4 v = *(const float4*)(X + (size_t)i * 4);
            uint32_t h0, l0, h1, l1;
            split2(v.x, v.y, h0, l0);
            split2(v.z, v.w, h1, l1);
            uint32_t* ph = (uint32_t*)(Xh + (size_t)i * 4);
            uint32_t* pl = (uint32_t*)(Xl + (size_t)i * 4);
            ph[0] = h0; ph[1] = h1; pl[0] = l0; pl[1] = l1;
        }
        return;
    }
    const float* W = (z == 0) ? W0 : (z == 1) ? W1 : (z == 2) ? W2 : W3;
    __nv_bfloat16* th = Th + (size_t)z * D_ * D_;
    __nv_bfloat16* tl = Tl + (size_t)z * D_ * D_;
    int k0 = blockIdx.x * 32, n0 = blockIdx.y * 32;
    int tx = threadIdx.x & 31, ty = threadIdx.x >> 5;
    #pragma unroll
    for (int j = ty; j < 32; j += 8)
        t[j][tx] = W[(size_t)(k0 + j) * D_ + n0 + tx];
    __syncthreads();
    #pragma unroll
    for (int j = ty; j < 32; j += 8) {
        float v = t[tx][j];
        __nv_bfloat16 h = __float2bfloat16(v);
        size_t o = (size_t)(n0 + j) * D_ + k0 + tx;
        th[o] = h;
        tl[o] = __float2bfloat16(v - __bfloat162float(h));
    }
}

// ---------------------------------------------------------------------------
// Shared GEMM mainloop: acc[4][4][4] for a 128x128 tile of (Ah+Al)@(Bh+Bl)^T.
// R16: ONE sync per k-tile. Order: wait(all) -> sync -> issue prefetch(kc+1)
// -> compute(kc). WAR on prefetch target covered by the top sync (its readers
// ran in iter kc-1, which completed before this sync).
// ---------------------------------------------------------------------------
#define KSTRIDE 80
#define TILE_B  10240
#define STAGE_B (4 * TILE_B)

__device__ __forceinline__ void gemm_mainloop(
    const __nv_bfloat16* gAh, const __nv_bfloat16* gAl,
    const __nv_bfloat16* gBh, const __nv_bfloat16* gBl,
    uint32_t smb, int tid, int lane, int wm, int wn,
    float acc[4][4][4])
{
    int li0 = tid, li1 = tid + 256;
    int lr0 = li0 >> 2, lc0 = (li0 & 3) * 8;
    int lr1 = li1 >> 2, lc1 = (li1 & 3) * 8;
    size_t go0 = (size_t)lr0 * D_ + lc0;
    size_t go1 = (size_t)lr1 * D_ + lc1;
    uint32_t so0 = (uint32_t)(lr0 * KSTRIDE + lc0 * 2);
    uint32_t so1 = (uint32_t)(lr1 * KSTRIDE + lc1 * 2);

    uint32_t a_off[4], b_off[4];
    #pragma unroll
    for (int i = 0; i < 4; ++i)
        a_off[i] = (uint32_t)((wm * 64 + i * 16 + (lane & 15)) * KSTRIDE
                              + (lane >> 4) * 16);
    #pragma unroll
    for (int j = 0; j < 4; ++j)
        b_off[j] = (uint32_t)((wn * 32 + j * 8 + (lane & 7)) * KSTRIDE
                              + ((lane >> 3) & 1) * 16);

    CP16(smb + 0*TILE_B + so0, gAh + go0);
    CP16(smb + 0*TILE_B + so1, gAh + go1);
    CP16(smb + 1*TILE_B + so0, gAl + go0);
    CP16(smb + 1*TILE_B + so1, gAl + go1);
    CP16(smb + 2*TILE_B + so0, gBh + go0);
    CP16(smb + 2*TILE_B + so1, gBh + go1);
    CP16(smb + 3*TILE_B + so0, gBl + go0);
    CP16(smb + 3*TILE_B + so1, gBl + go1);
    CPCOMMIT();

    for (int kc = 0; kc < 32; ++kc) {
        CPWAIT(0);
        __syncthreads();

        if (kc + 1 < 32) {
            size_t ko = (size_t)(kc + 1) * 32;
            uint32_t nb = smb + (uint32_t)((kc + 1) & 1) * STAGE_B;
            CP16(nb + 0*TILE_B + so0, gAh + go0 + ko);
            CP16(nb + 0*TILE_B + so1, gAh + go1 + ko);
            CP16(nb + 1*TILE_B + so0, gAl + go0 + ko);
            CP16(nb + 1*TILE_B + so1, gAl + go1 + ko);
            CP16(nb + 2*TILE_B + so0, gBh + go0 + ko);
            CP16(nb + 2*TILE_B + so1, gBh + go1 + ko);
            CP16(nb + 3*TILE_B + so0, gBl + go0 + ko);
            CP16(nb + 3*TILE_B + so1, gBl + go1 + ko);
            CPCOMMIT();
        }

        uint32_t st = smb + (uint32_t)(kc & 1) * STAGE_B;
        uint32_t sAh = st, sAl = st + TILE_B, sBh = st + 2 * TILE_B,
                 sBl = st + 3 * TILE_B;
        #pragma unroll
        for (int ks = 0; ks < 2; ++ks) {
            uint32_t kb = (uint32_t)(ks * 32);
            uint32_t ah[4][4], al[4][4], bh[4][2], bl[4][2];
            #pragma unroll
            for (int j = 0; j < 4; ++j) {
                ldmx2(bh[j][0], bh[j][1], sBh + b_off[j] + kb);
                ldmx2(bl[j][0], bl[j][1], sBl + b_off[j] + kb);
            }
            #pragma unroll
            for (int i = 0; i < 4; ++i) {
                ldmx4(ah[i][0], ah[i][1], ah[i][2], ah[i][3], sAh + a_off[i] + kb);
                ldmx4(al[i][0], al[i][1], al[i][2], al[i][3], sAl + a_off[i] + kb);
            }
            #pragma unroll
            for (int i = 0; i < 4; ++i)
                #pragma unroll
                for (int j = 0; j < 4; ++j) {
                    mma16816(acc[i][j], ah[i], bh[j]);
                    mma16816(acc[i][j], ah[i], bl[j]);
                    mma16816(acc[i][j], al[i], bh[j]);
                }
        }
    }
}

// ---------------------------------------------------------------------------
// Fused QKV projection GEMM. grid = (8, 32, 3): blockIdx.z selects Q/K/V.
// ---------------------------------------------------------------------------
__global__ __launch_bounds__(256, 2) void gemm_qkv(
    const __nv_bfloat16* __restrict__ Ah, const __nv_bfloat16* __restrict__ Al,
    const __nv_bfloat16* __restrict__ Wh, const __nv_bfloat16* __restrict__ Wl,
    const float* __restrict__ bq, const float* __restrict__ bk,
    const float* __restrict__ bv, const float* __restrict__ alpha,
    __nv_bfloat16* __restrict__ Qh, __nv_bfloat16* __restrict__ Ql,
    __nv_bfloat16* __restrict__ Kh, __nv_bfloat16* __restrict__ Kl,
    __nv_bfloat16* __restrict__ Vh, __nv_bfloat16* __restrict__ Vl)
{
    extern __shared__ char smraw[];
    const int tid  = threadIdx.x;
    const int lane = tid & 31;
    const int wid  = tid >> 5;
    const int wm   = wid >> 2;
    const int wn   = wid & 3;
    const int mat  = blockIdx.z;                // 0=Q,1=K,2=V
    const int c0   = blockIdx.x * 128;
    const int r0   = blockIdx.y * 128;

    const float* bvec = (mat == 0) ? bq : (mat == 1) ? bk : bv;
    __nv_bfloat16* outh = (mat == 0) ? Qh : (mat == 1) ? Kh : Vh;
    __nv_bfloat16* outl = (mat == 0) ? Ql : (mat == 1) ? Kl : Vl;

    float acc[4][4][4];
    #pragma unroll
    for (int i = 0; i < 4; ++i)
        #pragma unroll
        for (int j = 0; j < 4; ++j)
            #pragma unroll
            for (int e = 0; e < 4; ++e) acc[i][j][e] = 0.0f;

    gemm_mainloop(Ah + (size_t)r0 * D_, Al + (size_t)r0 * D_,
                  Wh + (size_t)mat * D_ * D_ + (size_t)c0 * D_,
                  Wl + (size_t)mat * D_ * D_ + (size_t)c0 * D_,
                  smem_u32(smraw), tid, lane, wm, wn, acc);

    #pragma unroll
    for (int i = 0; i < 4; ++i) {
        #pragma unroll
        for (int part = 0; part < 2; ++part) {
            int r = r0 + wm * 64 + i * 16 + (lane >> 2) + part * 8;
            float sc = (mat == 0) ? QSCALE : (1.0f + alpha[r]);
            int b = r >> 11, n = r & (N_ - 1);
            #pragma unroll
            for (int j = 0; j < 4; ++j) {
                int c = c0 + wn * 32 + j * 8 + (lane & 3) * 2;
                float v0 = (acc[i][j][part * 2 + 0] + bvec[c + 0]) * sc;
                float v1 = (acc[i][j][part * 2 + 1] + bvec[c + 1]) * sc;
                int hh = c >> 6, dk = c & 63;
                size_t off = (((size_t)(b * H_ + hh)) * N_ + n) * DK_ + dk;
                uint32_t uh, ul;
                split2(v0, v1, uh, ul);
                *(uint32_t*)(outh + off) = uh;
                *(uint32_t*)(outl + off) = ul;
            }
        }
    }
}

// ---------------------------------------------------------------------------
// Output projection GEMM (fp32 out += bias, row-major)
// ---------------------------------------------------------------------------
__global__ __launch_bounds__(256, 2) void gemm_out(
    const __nv_bfloat16* __restrict__ Ah, const __nv_bfloat16* __restrict__ Al,
    const __nv_bfloat16* __restrict__ Bh, const __nv_bfloat16* __restrict__ Bl,
    const float* __restrict__ bvec, float* __restrict__ outf)
{
    extern __shared__ char smraw[];
    const int tid  = threadIdx.x;
    const int lane = tid & 31;
    const int wid  = tid >> 5;
    const int wm   = wid >> 2;
    const int wn   = wid & 3;
    const int c0   = blockIdx.x * 128;
    const int r0   = blockIdx.y * 128;

    float acc[4][4][4];
    #pragma unroll
    for (int i = 0; i < 4; ++i)
        #pragma unroll
        for (int j = 0; j < 4; ++j)
            #pragma unroll
            for (int e = 0; e < 4; ++e) acc[i][j][e] = 0.0f;

    gemm_mainloop(Ah + (size_t)r0 * D_, Al + (size_t)r0 * D_,
                  Bh + (size_t)c0 * D_, Bl + (size_t)c0 * D_,
                  smem_u32(smraw), tid, lane, wm, wn, acc);

    #pragma unroll
    for (int i = 0; i < 4; ++i) {
        #pragma unroll
        for (int part = 0; part < 2; ++part) {
            int r = r0 + wm * 64 + i * 16 + (lane >> 2) + part * 8;
            #pragma unroll
            for (int j = 0; j < 4; ++j) {
                int c = c0 + wn * 32 + j * 8 + (lane & 3) * 2;
                float2 o;
                o.x = acc[i][j][part * 2 + 0] + bvec[c + 0];
                o.y = acc[i][j][part * 2 + 1] + bvec[c + 1];
                *(float2*)(outf + (size_t)r * D_ + c) = o;
            }
        }
    }
}

// ---------------------------------------------------------------------------
// Flash attention, mma.sync bf16 3-term split. 4 warps x m32 rows, 2 CTAs/SM.
// R16: ONE sync per key-tile (same wait->sync->prefetch->compute order).
// ---------------------------------------------------------------------------
#define QT    128
#define ATHR  128                // attn block size (4 warps)
#define VSTR  144                // bytes per smem row (64 bf16 + 8 pad)
#define ATILE (64 * VSTR)        // 9216 bytes per 64x64 bf16 tile

__global__ __launch_bounds__(ATHR, 2) void attn_mma(
    const __nv_bfloat16* __restrict__ Qh, const __nv_bfloat16* __restrict__ Ql,
    const __nv_bfloat16* __restrict__ Kh, const __nv_bfloat16* __restrict__ Kl,
    const __nv_bfloat16* __restrict__ Vh, const __nv_bfloat16* __restrict__ Vl,
    const float* __restrict__ bias,
    __nv_bfloat16* __restrict__ Yh, __nv_bfloat16* __restrict__ Yl)
{
    extern __shared__ char smraw[];
    const uint32_t sQh = smem_u32(smraw);
    const uint32_t sQl = sQh + QT * VSTR;
    const uint32_t sKV = sQl + QT * VSTR;   // 2 stages x {Kh,Kl,Vh,Vl}

    const int h   = blockIdx.x;
    const int qt  = blockIdx.y;
    const int b   = blockIdx.z;
    const int tid = threadIdx.x;
    const int lane = tid & 31;
    const int wq   = tid >> 5;          // 0..3, owns rows wq*32..+31
    const int q0   = qt * QT;

    const size_t headoff = ((size_t)(b * H_ + h)) * N_ * DK_;
    const __nv_bfloat16* gQh = Qh + headoff + (size_t)q0 * DK_;
    const __nv_bfloat16* gQl = Ql + headoff + (size_t)q0 * DK_;
    const __nv_bfloat16* gKh = Kh + headoff;
    const __nv_bfloat16* gKl = Kl + headoff;
    const __nv_bfloat16* gVh = Vh + headoff;
    const __nv_bfloat16* gVl = Vl + headoff;

    // Q tile load: 1024 float4 slots over 128 threads (visibility via the
    // first loop-top __syncthreads()).
    #pragma unroll
    for (int t = 0; t < 8; ++t) {
        int idx = tid + t * ATHR;
        int row = idx >> 3, c16 = idx & 7;
        uint32_t so = row * VSTR + c16 * 16;
        size_t   go = (size_t)row * DK_ + c16 * 8;
        *(float4*)(smraw + (sQh - smem_u32(smraw)) + so) = *(const float4*)(gQh + go);
        *(float4*)(smraw + (sQl - smem_u32(smraw)) + so) = *(const float4*)(gQl + go);
    }

    // stage 0 K/V: 2048 cp16 slots over 128 threads
    #pragma unroll
    for (int t = 0; t < 16; ++t) {
        int idx = tid + t * ATHR;
        int tile = idx >> 9;
        int w = idx & 511;
        int row = w >> 3, c16 = w & 7;
        const __nv_bfloat16* src =
            (tile == 0 ? gKh : tile == 1 ? gKl : tile == 2 ? gVh : gVl)
            + (size_t)row * DK_ + c16 * 8;
        CP16(sKV + tile * ATILE + row * VSTR + c16 * 16, src);
    }
    CPCOMMIT();

    // bias pointers: rows wq*32 + sub*16 + (lane>>2) + part*8
    const float* bpb = bias + ((size_t)b * N_ + q0 + wq * 32 + (lane >> 2)) * N_
                       + (lane & 3) * 2;

    float Oc0[8][4], Oc1[8][4];
    #pragma unroll
    for (int j = 0; j < 8; ++j)
        #pragma unroll
        for (int e = 0; e < 4; ++e) { Oc0[j][e] = 0.0f; Oc1[j][e] = 0.0f; }
    float l00 = 0.0f, l01 = 0.0f, l10 = 0.0f, l11 = 0.0f;

    for (int kt = 0; kt < 32; ++kt) {
        const int k0 = kt * 64;

        CPWAIT(0);
        __syncthreads();

        if (kt + 1 < 32) {
            uint32_t sb = sKV + (uint32_t)((kt + 1) & 1) * 4 * ATILE;
            int nk0 = k0 + 64;
            #pragma unroll
            for (int t = 0; t < 16; ++t) {
                int idx = tid + t * ATHR;
                int tile = idx >> 9;
                int w = idx & 511;
                int row = w >> 3, c16 = w & 7;
                const __nv_bfloat16* src =
                    (tile == 0 ? gKh : tile == 1 ? gKl : tile == 2 ? gVh : gVl)
                    + (size_t)(nk0 + row) * DK_ + c16 * 8;
                CP16(sb + tile * ATILE + row * VSTR + c16 * 16, src);
            }
            CPCOMMIT();
        }

        // Sc init from bias*log2e (sub0 rows +0/+8, sub1 rows +16/+24)
        float Sc0[8][4], Sc1[8][4];
        #pragma unroll
        for (int j = 0; j < 8; ++j) {
            float2 a0 = *(const float2*)(bpb + 0  * (size_t)N_ + k0 + j * 8);
            float2 a1 = *(const float2*)(bpb + 8  * (size_t)N_ + k0 + j * 8);
            float2 a2 = *(const float2*)(bpb + 16 * (size_t)N_ + k0 + j * 8);
            float2 a3 = *(const float2*)(bpb + 24 * (size_t)N_ + k0 + j * 8);
            Sc0[j][0] = a0.x * LOG2E; Sc0[j][1] = a0.y * LOG2E;
            Sc0[j][2] = a1.x * LOG2E; Sc0[j][3] = a1.y * LOG2E;
            Sc1[j][0] = a2.x * LOG2E; Sc1[j][1] = a2.y * LOG2E;
            Sc1[j][2] = a3.x * LOG2E; Sc1[j][3] = a3.y * LOG2E;
        }

        uint32_t st = sKV + (uint32_t)(kt & 1) * 4 * ATILE;
        uint32_t sKh_ = st, sKl_ = st + ATILE, sVh_ = st + 2 * ATILE,
                 sVl_ = st + 3 * ATILE;

        // ---- S for both m16 subs; K frags loaded once per (ks, jj) ----
        #pragma unroll
        for (int ks = 0; ks < 4; ++ks) {
            uint32_t qa0 = (uint32_t)((wq * 32 + (lane & 15)) * VSTR
                                      + (lane >> 4) * 16 + ks * 32);
            uint32_t qa1 = qa0 + 16 * VSTR;
            uint32_t qh0[4], ql0[4], qh1[4], ql1[4];
            ldmx4(qh0[0], qh0[1], qh0[2], qh0[3], sQh + qa0);
            ldmx4(ql0[0], ql0[1], ql0[2], ql0[3], sQl + qa0);
            ldmx4(qh1[0], qh1[1], qh1[2], qh1[3], sQh + qa1);
            ldmx4(ql1[0], ql1[1], ql1[2], ql1[3], sQl + qa1);
            #pragma unroll
            for (int jp = 0; jp < 2; ++jp) {
                uint32_t kh[4][2], kl[4][2];
                #pragma unroll
                for (int jj = 0; jj < 4; jj += 2) {
                    uint32_t r0, r1, r2, r3;
                    uint32_t a2 = (uint32_t)(((jp * 4 + jj) * 8 + (lane & 15)) * VSTR
                                             + ks * 32 + (lane >> 4) * 16);
                    ldmx4(r0, r1, r2, r3, sKh_ + a2);
                    kh[jj][0] = r0; kh[jj][1] = r2;
                    kh[jj+1][0] = r1; kh[jj+1][1] = r3;
                    ldmx4(r0, r1, r2, r3, sKl_ + a2);
                    kl[jj][0] = r0; kl[jj][1] = r2;
                    kl[jj+1][0] = r1; kl[jj+1][1] = r3;
                }
                #pragma unroll
                for (int jj = 0; jj < 4; ++jj) {
                    int j = jp * 4 + jj;
                    mma16816(Sc0[j], qh0, kh[jj]);
                    mma16816(Sc0[j], qh0, kl[jj]);
                    mma16816(Sc0[j], ql0, kh[jj]);
                    mma16816(Sc1[j], qh1, kh[jj]);
                    mma16816(Sc1[j], qh1, kl[jj]);
                    mma16816(Sc1[j], ql1, kh[jj]);
                }
            }
        }

        // ---- fused exp2 + denominators + P-split, per ks pair ----
        uint32_t pha0[4][4], pla0[4][4], pha1[4][4], pla1[4][4];
        #pragma unroll
        for (int ks = 0; ks < 4; ++ks) {
            float e0, e1, e2, e3;
            e0 = ex2(Sc0[2*ks][0]);   e1 = ex2(Sc0[2*ks][1]);
            e2 = ex2(Sc0[2*ks][2]);   e3 = ex2(Sc0[2*ks][3]);
            l00 += e0 + e1; l01 += e2 + e3;
            split2(e0, e1, pha0[ks][0], pla0[ks][0]);
            split2(e2, e3, pha0[ks][1], pla0[ks][1]);
            e0 = ex2(Sc0[2*ks+1][0]); e1 = ex2(Sc0[2*ks+1][1]);
            e2 = ex2(Sc0[2*ks+1][2]); e3 = ex2(Sc0[2*ks+1][3]);
            l00 += e0 + e1; l01 += e2 + e3;
            split2(e0, e1, pha0[ks][2], pla0[ks][2]);
            split2(e2, e3, pha0[ks][3], pla0[ks][3]);

            e0 = ex2(Sc1[2*ks][0]);   e1 = ex2(Sc1[2*ks][1]);
            e2 = ex2(Sc1[2*ks][2]);   e3 = ex2(Sc1[2*ks][3]);
            l10 += e0 + e1; l11 += e2 + e3;
            split2(e0, e1, pha1[ks][0], pla1[ks][0]);
            split2(e2, e3, pha1[ks][1], pla1[ks][1]);
            e0 = ex2(Sc1[2*ks+1][0]); e1 = ex2(Sc1[2*ks+1][1]);
            e2 = ex2(Sc1[2*ks+1][2]); e3 = ex2(Sc1[2*ks+1][3]);
            l10 += e0 + e1; l11 += e2 + e3;
            split2(e0, e1, pha1[ks][2], pla1[ks][2]);
            split2(e2, e3, pha1[ks][3], pla1[ks][3]);
        }

        // ---- O += P V; V frags loaded once per jd, used by both subs ----
        #pragma unroll
        for (int jd = 0; jd < 8; ++jd) {
            uint32_t vh[4][2], vl[4][2];
            #pragma unroll
            for (int kp = 0; kp < 2; ++kp) {
                uint32_t ao = (uint32_t)((kp * 32 + lane) * VSTR + jd * 16);
                uint32_t r0, r1, r2, r3;
                ldmx4t(r0, r1, r2, r3, sVh_ + ao);
                vh[2*kp][0] = r0; vh[2*kp][1] = r1;
                vh[2*kp+1][0] = r2; vh[2*kp+1][1] = r3;
                ldmx4t(r0, r1, r2, r3, sVl_ + ao);
                vl[2*kp][0] = r0; vl[2*kp][1] = r1;
                vl[2*kp+1][0] = r2; vl[2*kp+1][1] = r3;
            }
            #pragma unroll
            for (int ks = 0; ks < 4; ++ks) {
                mma16816(Oc0[jd], pha0[ks], vh[ks]);
                mma16816(Oc0[jd], pha0[ks], vl[ks]);
                mma16816(Oc0[jd], pla0[ks], vh[ks]);
                mma16816(Oc1[jd], pha1[ks], vh[ks]);
                mma16816(Oc1[jd], pha1[ks], vl[ks]);
                mma16816(Oc1[jd], pla1[ks], vh[ks]);
            }
        }
    }

    // ---- deferred denominator reduction ----
    l00 += __shfl_xor_sync(0xffffffffu, l00, 1);
    l00 += __shfl_xor_sync(0xffffffffu, l00, 2);
    l01 += __shfl_xor_sync(0xffffffffu, l01, 1);
    l01 += __shfl_xor_sync(0xffffffffu, l01, 2);
    l10 += __shfl_xor_sync(0xffffffffu, l10, 1);
    l10 += __shfl_xor_sync(0xffffffffu, l10, 2);
    l11 += __shfl_xor_sync(0xffffffffu, l11, 1);
    l11 += __shfl_xor_sync(0xffffffffu, l11, 2);

    float i00 = 1.0f / l00, i01 = 1.0f / l01;
    float i10 = 1.0f / l10, i11 = 1.0f / l11;
    size_t rg = ((size_t)b * N_ + q0 + wq * 32 + (lane >> 2)) * D_
                + h * 64 + (lane & 3) * 2;
    #pragma unroll
    for (int jd = 0; jd < 8; ++jd) {
        uint32_t uh, ul;
        split2(Oc0[jd][0] * i00, Oc0[jd][1] * i00, uh, ul);
        *(uint32_t*)(Yh + rg + 0 * (size_t)D_ + jd * 8) = uh;
        *(uint32_t*)(Yl + rg + 0 * (size_t)D_ + jd * 8) = ul;
        split2(Oc0[jd][2] * i01, Oc0[jd][3] * i01, uh, ul);
        *(uint32_t*)(Yh + rg + 8 * (size_t)D_ + jd * 8) = uh;
        *(uint32_t*)(Yl + rg + 8 * (size_t)D_ + jd * 8) = ul;
        split2(Oc1[jd][0] * i10, Oc1[jd][1] * i10, uh, ul);
        *(uint32_t*)(Yh + rg + 16 * (size_t)D_ + jd * 8) = uh;
        *(uint32_t*)(Yl + rg + 16 * (size_t)D_ + jd * 8) = ul;
        split2(Oc1[jd][2] * i11, Oc1[jd][3] * i11, uh, ul);
        *(uint32_t*)(Yh + rg + 24 * (size_t)D_ + jd * 8) = uh;
        *(uint32_t*)(Yl + rg + 24 * (size_t)D_ + jd * 8) = ul;
    }
}

// ---------------------------------------------------------------------------
extern "C" void kernel_launch(void* const* d_in, const int* in_sizes, int n_in,
                              void* d_out, int out_size)
{
    const float* x     = (const float*)d_in[0];
    const float* alpha = (const float*)d_in[1];
    const float* bias  = (const float*)d_in[2];
    const float* Wq    = (const float*)d_in[3];
    const float* bq    = (const float*)d_in[4];
    const float* Wk    = (const float*)d_in[5];
    const float* bk    = (const float*)d_in[6];
    const float* Wv    = (const float*)d_in[7];
    const float* bv    = (const float*)d_in[8];
    const float* Wo    = (const float*)d_in[9];
    const float* bo    = (const float*)d_in[10];
    float* out = (float*)d_out;

    __nv_bfloat16 *ahp, *alp, *whp, *wlp, *qhp, *qlp, *khp, *klp, *vhp, *vlp;
    cudaGetSymbolAddress((void**)&ahp, g_Ah);
    cudaGetSymbolAddress((void**)&alp, g_Al);
    cudaGetSymbolAddress((void**)&whp, g_Wh);
    cudaGetSymbolAddress((void**)&wlp, g_Wl);
    cudaGetSymbolAddress((void**)&qhp, g_Qh);
    cudaGetSymbolAddress((void**)&qlp, g_Ql);
    cudaGetSymbolAddress((void**)&khp, g_Kh);
    cudaGetSymbolAddress((void**)&klp, g_Kl);
    cudaGetSymbolAddress((void**)&vhp, g_Vh);
    cudaGetSymbolAddress((void**)&vlp, g_Vl);

    const int gemm_smem = 2 * STAGE_B;                       // 81920
    cudaFuncSetAttribute(gemm_qkv, cudaFuncAttributeMaxDynamicSharedMemorySize,
                         gemm_smem);
    cudaFuncSetAttribute(gemm_out, cudaFuncAttributeMaxDynamicSharedMemorySize,
                         gemm_smem);
    const int attn_smem = 2 * QT * VSTR + 2 * 4 * ATILE;     // 110592
    cudaFuncSetAttribute(attn_mma, cudaFuncAttributeMaxDynamicSharedMemorySize,
                         attn_smem);

    dim3 blk(256);
    prep_kernel<<<dim3(32, 32, 5), blk>>>(x, Wq, Wk, Wv, Wo, whp, wlp, ahp, alp);

    gemm_qkv<<<dim3(8, 32, 3), blk, gemm_smem>>>(
        ahp, alp, whp, wlp, bq, bk, bv, alpha,
        qhp, qlp, khp, klp, vhp, vlp);

    attn_mma<<<dim3(H_, N_ / QT, B_), dim3(ATHR), attn_smem>>>(
        qhp, qlp, khp, klp, vhp, vlp, bias, ahp, alp);

    gemm_out<<<dim3(8, 32), blk, gemm_smem>>>(
        ahp, alp, whp + 3 * (size_t)D_ * D_, wlp + 3 * (size_t)D_ * D_, bo, out);
}

// round 17
// speedup vs baseline: 1.0073x; 1.0073x over previous
#include <cuda_runtime.h>
#include <cuda_bf16.h>
#include <cstdint>
#include <math.h>

#define B_   2
#define N_   2048
#define D_   1024
#define H_   16
#define DK_  64
#define M_   (B_ * N_)   // 4096

#define QSCALE 0.1803368801111204f   // 0.125 * log2(e)
#define LOG2E  1.4426950408889634f

// ---------------- scratch (allocation-free rule: __device__ globals) -------
__device__ __nv_bfloat16 g_Ah[M_ * D_];     // x split, later Y split
__device__ __nv_bfloat16 g_Al[M_ * D_];
__device__ __nv_bfloat16 g_Wh[4][D_ * D_];  // transposed weights [n][k], hi
__device__ __nv_bfloat16 g_Wl[4][D_ * D_];  // lo
__device__ __nv_bfloat16 g_Qh[B_ * H_ * N_ * DK_];
__device__ __nv_bfloat16 g_Ql[B_ * H_ * N_ * DK_];
__device__ __nv_bfloat16 g_Kh[B_ * H_ * N_ * DK_];
__device__ __nv_bfloat16 g_Kl[B_ * H_ * N_ * DK_];
__device__ __nv_bfloat16 g_Vh[B_ * H_ * N_ * DK_];
__device__ __nv_bfloat16 g_Vl[B_ * H_ * N_ * DK_];

// ---------------- PTX helpers (baseline ISA: sm_80-level only) -------------
__device__ __forceinline__ uint32_t smem_u32(const void* p) {
    uint32_t a;
    asm("{ .reg .u64 t; cvta.to.shared.u64 t, %1; cvt.u32.u64 %0, t; }"
        : "=r"(a) : "l"(p));
    return a;
}
__device__ __forceinline__ void ldmx4(uint32_t& r0, uint32_t& r1,
                                      uint32_t& r2, uint32_t& r3, uint32_t a) {
    asm volatile("ldmatrix.sync.aligned.m8n8.x4.shared.b16 {%0,%1,%2,%3}, [%4];"
                 : "=r"(r0), "=r"(r1), "=r"(r2), "=r"(r3) : "r"(a));
}
__device__ __forceinline__ void ldmx4t(uint32_t& r0, uint32_t& r1,
                                       uint32_t& r2, uint32_t& r3, uint32_t a) {
    asm volatile("ldmatrix.sync.aligned.m8n8.x4.trans.shared.b16 {%0,%1,%2,%3}, [%4];"
                 : "=r"(r0), "=r"(r1), "=r"(r2), "=r"(r3) : "r"(a));
}
__device__ __forceinline__ void ldmx2(uint32_t& r0, uint32_t& r1, uint32_t a) {
    asm volatile("ldmatrix.sync.aligned.m8n8.x2.shared.b16 {%0,%1}, [%2];"
                 : "=r"(r0), "=r"(r1) : "r"(a));
}
__device__ __forceinline__ void mma16816(float* c, const uint32_t* a,
                                         const uint32_t* b) {
    asm volatile(
        "mma.sync.aligned.m16n8k16.row.col.f32.bf16.bf16.f32 "
        "{%0,%1,%2,%3}, {%4,%5,%6,%7}, {%8,%9}, {%0,%1,%2,%3};"
        : "+f"(c[0]), "+f"(c[1]), "+f"(c[2]), "+f"(c[3])
        : "r"(a[0]), "r"(a[1]), "r"(a[2]), "r"(a[3]), "r"(b[0]), "r"(b[1]));
}
__device__ __forceinline__ float ex2(float x) {
    float r;
    asm("ex2.approx.ftz.f32 %0, %1;" : "=f"(r) : "f"(x));
    return r;
}
__device__ __forceinline__ void split2(float x, float y, uint32_t& h, uint32_t& l) {
    __nv_bfloat16 hx = __float2bfloat16(x), hy = __float2bfloat16(y);
    __nv_bfloat16 lx = __float2bfloat16(x - __bfloat162float(hx));
    __nv_bfloat16 ly = __float2bfloat16(y - __bfloat162float(hy));
    __nv_bfloat162 hp(hx, hy), lp(lx, ly);
    h = *(uint32_t*)&hp; l = *(uint32_t*)&lp;
}
#define CP16(dst, src) \
    asm volatile("cp.async.ca.shared.global [%0], [%1], 16;" :: "r"(dst), "l"(src))
#define CPCOMMIT() asm volatile("cp.async.commit_group;" ::: "memory")
#define CPWAIT(n)  asm volatile("cp.async.wait_group %0;" :: "n"(n) : "memory")

// ---------------------------------------------------------------------------
// prep: grid (32,32,5). z<4: W[z] transpose+split. z==4: x elementwise split.
// ---------------------------------------------------------------------------
__global__ __launch_bounds__(256) void prep_kernel(
    const float* __restrict__ X,
    const float* __restrict__ W0, const float* __restrict__ W1,
    const float* __restrict__ W2, const float* __restrict__ W3,
    __nv_bfloat16* __restrict__ Th, __nv_bfloat16* __restrict__ Tl,
    __nv_bfloat16* __restrict__ Xh, __nv_bfloat16* __restrict__ Xl)
{
    __shared__ float t[32][33];
    const int z = blockIdx.z;
    if (z == 4) {
        int base = (blockIdx.x * 32 + blockIdx.y) * 256 + threadIdx.x;
        #pragma unroll
        for (int tt = 0; tt < 4; ++tt) {
            int i = base + tt * 262144;
            float4 v = *(const float4*)(X + (size_t)i * 4);
            uint32_t h0, l0, h1, l1;
            split2(v.x, v.y, h0, l0);
            split2(v.z, v.w, h1, l1);
            uint32_t* ph = (uint32_t*)(Xh + (size_t)i * 4);
            uint32_t* pl = (uint32_t*)(Xl + (size_t)i * 4);
            ph[0] = h0; ph[1] = h1; pl[0] = l0; pl[1] = l1;
        }
        return;
    }
    const float* W = (z == 0) ? W0 : (z == 1) ? W1 : (z == 2) ? W2 : W3;
    __nv_bfloat16* th = Th + (size_t)z * D_ * D_;
    __nv_bfloat16* tl = Tl + (size_t)z * D_ * D_;
    int k0 = blockIdx.x * 32, n0 = blockIdx.y * 32;
    int tx = threadIdx.x & 31, ty = threadIdx.x >> 5;
    #pragma unroll
    for (int j = ty; j < 32; j += 8)
        t[j][tx] = W[(size_t)(k0 + j) * D_ + n0 + tx];
    __syncthreads();
    #pragma unroll
    for (int j = ty; j < 32; j += 8) {
        float v = t[tx][j];
        __nv_bfloat16 h = __float2bfloat16(v);
        size_t o = (size_t)(n0 + j) * D_ + k0 + tx;
        th[o] = h;
        tl[o] = __float2bfloat16(v - __bfloat162float(h));
    }
}

// ---------------------------------------------------------------------------
// Shared GEMM mainloop (R11/R9 proven config): acc[4][4][4] for a 128x128
// tile of (Ah+Al)@(Bh+Bl)^T. cp.async double buffer -> 2 CTAs/SM.
// B loaded via 8-row ldmx2 (conflict-free on the 80B-stride layout).
// ---------------------------------------------------------------------------
#define KSTRIDE 80
#define TILE_B  10240
#define STAGE_B (4 * TILE_B)

__device__ __forceinline__ void gemm_mainloop(
    const __nv_bfloat16* gAh, const __nv_bfloat16* gAl,
    const __nv_bfloat16* gBh, const __nv_bfloat16* gBl,
    uint32_t smb, int tid, int lane, int wm, int wn,
    float acc[4][4][4])
{
    int li0 = tid, li1 = tid + 256;
    int lr0 = li0 >> 2, lc0 = (li0 & 3) * 8;
    int lr1 = li1 >> 2, lc1 = (li1 & 3) * 8;
    size_t go0 = (size_t)lr0 * D_ + lc0;
    size_t go1 = (size_t)lr1 * D_ + lc1;
    uint32_t so0 = (uint32_t)(lr0 * KSTRIDE + lc0 * 2);
    uint32_t so1 = (uint32_t)(lr1 * KSTRIDE + lc1 * 2);

    uint32_t a_off[4], b_off[4];
    #pragma unroll
    for (int i = 0; i < 4; ++i)
        a_off[i] = (uint32_t)((wm * 64 + i * 16 + (lane & 15)) * KSTRIDE
                              + (lane >> 4) * 16);
    #pragma unroll
    for (int j = 0; j < 4; ++j)
        b_off[j] = (uint32_t)((wn * 32 + j * 8 + (lane & 7)) * KSTRIDE
                              + ((lane >> 3) & 1) * 16);

    CP16(smb + 0*TILE_B + so0, gAh + go0);
    CP16(smb + 0*TILE_B + so1, gAh + go1);
    CP16(smb + 1*TILE_B + so0, gAl + go0);
    CP16(smb + 1*TILE_B + so1, gAl + go1);
    CP16(smb + 2*TILE_B + so0, gBh + go0);
    CP16(smb + 2*TILE_B + so1, gBh + go1);
    CP16(smb + 3*TILE_B + so0, gBl + go0);
    CP16(smb + 3*TILE_B + so1, gBl + go1);
    CPCOMMIT();

    for (int kc = 0; kc < 32; ++kc) {
        if (kc + 1 < 32) {
            size_t ko = (size_t)(kc + 1) * 32;
            uint32_t nb = smb + (uint32_t)((kc + 1) & 1) * STAGE_B;
            CP16(nb + 0*TILE_B + so0, gAh + go0 + ko);
            CP16(nb + 0*TILE_B + so1, gAh + go1 + ko);
            CP16(nb + 1*TILE_B + so0, gAl + go0 + ko);
            CP16(nb + 1*TILE_B + so1, gAl + go1 + ko);
            CP16(nb + 2*TILE_B + so0, gBh + go0 + ko);
            CP16(nb + 2*TILE_B + so1, gBh + go1 + ko);
            CP16(nb + 3*TILE_B + so0, gBl + go0 + ko);
            CP16(nb + 3*TILE_B + so1, gBl + go1 + ko);
            CPCOMMIT();
            CPWAIT(1);
        } else {
            CPWAIT(0);
        }
        __syncthreads();

        uint32_t st = smb + (uint32_t)(kc & 1) * STAGE_B;
        uint32_t sAh = st, sAl = st + TILE_B, sBh = st + 2 * TILE_B,
                 sBl = st + 3 * TILE_B;
        #pragma unroll
        for (int ks = 0; ks < 2; ++ks) {
            uint32_t kb = (uint32_t)(ks * 32);
            uint32_t ah[4][4], al[4][4], bh[4][2], bl[4][2];
            #pragma unroll
            for (int j = 0; j < 4; ++j) {
                ldmx2(bh[j][0], bh[j][1], sBh + b_off[j] + kb);
                ldmx2(bl[j][0], bl[j][1], sBl + b_off[j] + kb);
            }
            #pragma unroll
            for (int i = 0; i < 4; ++i) {
                ldmx4(ah[i][0], ah[i][1], ah[i][2], ah[i][3], sAh + a_off[i] + kb);
                ldmx4(al[i][0], al[i][1], al[i][2], al[i][3], sAl + a_off[i] + kb);
            }
            #pragma unroll
            for (int i = 0; i < 4; ++i)
                #pragma unroll
                for (int j = 0; j < 4; ++j) {
                    mma16816(acc[i][j], ah[i], bh[j]);
                    mma16816(acc[i][j], ah[i], bl[j]);
                    mma16816(acc[i][j], al[i], bh[j]);
                }
        }
        __syncthreads();
    }
}

// ---------------------------------------------------------------------------
// Fused QKV projection GEMM. grid = (8, 32, 3): blockIdx.z selects Q/K/V.
// ---------------------------------------------------------------------------
__global__ __launch_bounds__(256, 2) void gemm_qkv(
    const __nv_bfloat16* __restrict__ Ah, const __nv_bfloat16* __restrict__ Al,
    const __nv_bfloat16* __restrict__ Wh, const __nv_bfloat16* __restrict__ Wl,
    const float* __restrict__ bq, const float* __restrict__ bk,
    const float* __restrict__ bv, const float* __restrict__ alpha,
    __nv_bfloat16* __restrict__ Qh, __nv_bfloat16* __restrict__ Ql,
    __nv_bfloat16* __restrict__ Kh, __nv_bfloat16* __restrict__ Kl,
    __nv_bfloat16* __restrict__ Vh, __nv_bfloat16* __restrict__ Vl)
{
    extern __shared__ char smraw[];
    const int tid  = threadIdx.x;
    const int lane = tid & 31;
    const int wid  = tid >> 5;
    const int wm   = wid >> 2;
    const int wn   = wid & 3;
    const int mat  = blockIdx.z;                // 0=Q,1=K,2=V
    const int c0   = blockIdx.x * 128;
    const int r0   = blockIdx.y * 128;

    const float* bvec = (mat == 0) ? bq : (mat == 1) ? bk : bv;
    __nv_bfloat16* outh = (mat == 0) ? Qh : (mat == 1) ? Kh : Vh;
    __nv_bfloat16* outl = (mat == 0) ? Ql : (mat == 1) ? Kl : Vl;

    float acc[4][4][4];
    #pragma unroll
    for (int i = 0; i < 4; ++i)
        #pragma unroll
        for (int j = 0; j < 4; ++j)
            #pragma unroll
            for (int e = 0; e < 4; ++e) acc[i][j][e] = 0.0f;

    gemm_mainloop(Ah + (size_t)r0 * D_, Al + (size_t)r0 * D_,
                  Wh + (size_t)mat * D_ * D_ + (size_t)c0 * D_,
                  Wl + (size_t)mat * D_ * D_ + (size_t)c0 * D_,
                  smem_u32(smraw), tid, lane, wm, wn, acc);

    #pragma unroll
    for (int i = 0; i < 4; ++i) {
        #pragma unroll
        for (int part = 0; part < 2; ++part) {
            int r = r0 + wm * 64 + i * 16 + (lane >> 2) + part * 8;
            float sc = (mat == 0) ? QSCALE : (1.0f + alpha[r]);
            int b = r >> 11, n = r & (N_ - 1);
            #pragma unroll
            for (int j = 0; j < 4; ++j) {
                int c = c0 + wn * 32 + j * 8 + (lane & 3) * 2;
                float v0 = (acc[i][j][part * 2 + 0] + bvec[c + 0]) * sc;
                float v1 = (acc[i][j][part * 2 + 1] + bvec[c + 1]) * sc;
                int hh = c >> 6, dk = c & 63;
                size_t off = (((size_t)(b * H_ + hh)) * N_ + n) * DK_ + dk;
                uint32_t uh, ul;
                split2(v0, v1, uh, ul);
                *(uint32_t*)(outh + off) = uh;
                *(uint32_t*)(outl + off) = ul;
            }
        }
    }
}

// ---------------------------------------------------------------------------
// Output projection GEMM (fp32 out += bias, row-major)
// ---------------------------------------------------------------------------
__global__ __launch_bounds__(256, 2) void gemm_out(
    const __nv_bfloat16* __restrict__ Ah, const __nv_bfloat16* __restrict__ Al,
    const __nv_bfloat16* __restrict__ Bh, const __nv_bfloat16* __restrict__ Bl,
    const float* __restrict__ bvec, float* __restrict__ outf)
{
    extern __shared__ char smraw[];
    const int tid  = threadIdx.x;
    const int lane = tid & 31;
    const int wid  = tid >> 5;
    const int wm   = wid >> 2;
    const int wn   = wid & 3;
    const int c0   = blockIdx.x * 128;
    const int r0   = blockIdx.y * 128;

    float acc[4][4][4];
    #pragma unroll
    for (int i = 0; i < 4; ++i)
        #pragma unroll
        for (int j = 0; j < 4; ++j)
            #pragma unroll
            for (int e = 0; e < 4; ++e) acc[i][j][e] = 0.0f;

    gemm_mainloop(Ah + (size_t)r0 * D_, Al + (size_t)r0 * D_,
                  Bh + (size_t)c0 * D_, Bl + (size_t)c0 * D_,
                  smem_u32(smraw), tid, lane, wm, wn, acc);

    #pragma unroll
    for (int i = 0; i < 4; ++i) {
        #pragma unroll
        for (int part = 0; part < 2; ++part) {
            int r = r0 + wm * 64 + i * 16 + (lane >> 2) + part * 8;
            #pragma unroll
            for (int j = 0; j < 4; ++j) {
                int c = c0 + wn * 32 + j * 8 + (lane & 3) * 2;
                float2 o;
                o.x = acc[i][j][part * 2 + 0] + bvec[c + 0];
                o.y = acc[i][j][part * 2 + 1] + bvec[c + 1];
                *(float2*)(outf + (size_t)r * D_ + c) = o;
            }
        }
    }
}

// ---------------------------------------------------------------------------
// Flash attention, mma.sync bf16 3-term split. 4 warps x m32 rows, 2 CTAs/SM.
// (R11/R15 configuration — best measured.)
// ---------------------------------------------------------------------------
#define QT    128
#define ATHR  128                // attn block size (4 warps)
#define VSTR  144                // bytes per smem row (64 bf16 + 8 pad)
#define ATILE (64 * VSTR)        // 9216 bytes per 64x64 bf16 tile

__global__ __launch_bounds__(ATHR, 2) void attn_mma(
    const __nv_bfloat16* __restrict__ Qh, const __nv_bfloat16* __restrict__ Ql,
    const __nv_bfloat16* __restrict__ Kh, const __nv_bfloat16* __restrict__ Kl,
    const __nv_bfloat16* __restrict__ Vh, const __nv_bfloat16* __restrict__ Vl,
    const float* __restrict__ bias,
    __nv_bfloat16* __restrict__ Yh, __nv_bfloat16* __restrict__ Yl)
{
    extern __shared__ char smraw[];
    const uint32_t sQh = smem_u32(smraw);
    const uint32_t sQl = sQh + QT * VSTR;
    const uint32_t sKV = sQl + QT * VSTR;   // 2 stages x {Kh,Kl,Vh,Vl}

    const int h   = blockIdx.x;
    const int qt  = blockIdx.y;
    const int b   = blockIdx.z;
    const int tid = threadIdx.x;
    const int lane = tid & 31;
    const int wq   = tid >> 5;          // 0..3, owns rows wq*32..+31
    const int q0   = qt * QT;

    const size_t headoff = ((size_t)(b * H_ + h)) * N_ * DK_;
    const __nv_bfloat16* gQh = Qh + headoff + (size_t)q0 * DK_;
    const __nv_bfloat16* gQl = Ql + headoff + (size_t)q0 * DK_;
    const __nv_bfloat16* gKh = Kh + headoff;
    const __nv_bfloat16* gKl = Kl + headoff;
    const __nv_bfloat16* gVh = Vh + headoff;
    const __nv_bfloat16* gVl = Vl + headoff;

    // Q tile load: 1024 float4 slots over 128 threads
    #pragma unroll
    for (int t = 0; t < 8; ++t) {
        int idx = tid + t * ATHR;
        int row = idx >> 3, c16 = idx & 7;
        uint32_t so = row * VSTR + c16 * 16;
        size_t   go = (size_t)row * DK_ + c16 * 8;
        *(float4*)(smraw + (sQh - smem_u32(smraw)) + so) = *(const float4*)(gQh + go);
        *(float4*)(smraw + (sQl - smem_u32(smraw)) + so) = *(const float4*)(gQl + go);
    }

    // stage 0 K/V: 2048 cp16 slots over 128 threads
    #pragma unroll
    for (int t = 0; t < 16; ++t) {
        int idx = tid + t * ATHR;
        int tile = idx >> 9;
        int w = idx & 511;
        int row = w >> 3, c16 = w & 7;
        const __nv_bfloat16* src =
            (tile == 0 ? gKh : tile == 1 ? gKl : tile == 2 ? gVh : gVl)
            + (size_t)row * DK_ + c16 * 8;
        CP16(sKV + tile * ATILE + row * VSTR + c16 * 16, src);
    }
    CPCOMMIT();

    __syncthreads();

    // bias pointers: rows wq*32 + sub*16 + (lane>>2) + part*8
    const float* bpb = bias + ((size_t)b * N_ + q0 + wq * 32 + (lane >> 2)) * N_
                       + (lane & 3) * 2;

    float Oc0[8][4], Oc1[8][4];
    #pragma unroll
    for (int j = 0; j < 8; ++j)
        #pragma unroll
        for (int e = 0; e < 4; ++e) { Oc0[j][e] = 0.0f; Oc1[j][e] = 0.0f; }
    float l00 = 0.0f, l01 = 0.0f, l10 = 0.0f, l11 = 0.0f;

    for (int kt = 0; kt < 32; ++kt) {
        const int k0 = kt * 64;

        // Sc init from bias*log2e (sub0 rows +0/+8, sub1 rows +16/+24)
        float Sc0[8][4], Sc1[8][4];
        #pragma unroll
        for (int j = 0; j < 8; ++j) {
            float2 a0 = *(const float2*)(bpb + 0  * (size_t)N_ + k0 + j * 8);
            float2 a1 = *(const float2*)(bpb + 8  * (size_t)N_ + k0 + j * 8);
            float2 a2 = *(const float2*)(bpb + 16 * (size_t)N_ + k0 + j * 8);
            float2 a3 = *(const float2*)(bpb + 24 * (size_t)N_ + k0 + j * 8);
            Sc0[j][0] = a0.x * LOG2E; Sc0[j][1] = a0.y * LOG2E;
            Sc0[j][2] = a1.x * LOG2E; Sc0[j][3] = a1.y * LOG2E;
            Sc1[j][0] = a2.x * LOG2E; Sc1[j][1] = a2.y * LOG2E;
            Sc1[j][2] = a3.x * LOG2E; Sc1[j][3] = a3.y * LOG2E;
        }

        if (kt + 1 < 32) {
            uint32_t sb = sKV + (uint32_t)((kt + 1) & 1) * 4 * ATILE;
            int nk0 = k0 + 64;
            #pragma unroll
            for (int t = 0; t < 16; ++t) {
                int idx = tid + t * ATHR;
                int tile = idx >> 9;
                int w = idx & 511;
                int row = w >> 3, c16 = w & 7;
                const __nv_bfloat16* src =
                    (tile == 0 ? gKh : tile == 1 ? gKl : tile == 2 ? gVh : gVl)
                    + (size_t)(nk0 + row) * DK_ + c16 * 8;
                CP16(sb + tile * ATILE + row * VSTR + c16 * 16, src);
            }
            CPCOMMIT();
            CPWAIT(1);
        } else {
            CPWAIT(0);
        }
        __syncthreads();

        uint32_t st = sKV + (uint32_t)(kt & 1) * 4 * ATILE;
        uint32_t sKh_ = st, sKl_ = st + ATILE, sVh_ = st + 2 * ATILE,
                 sVl_ = st + 3 * ATILE;

        // ---- S for both m16 subs; K frags loaded once per (ks, jj) ----
        #pragma unroll
        for (int ks = 0; ks < 4; ++ks) {
            uint32_t qa0 = (uint32_t)((wq * 32 + (lane & 15)) * VSTR
                                      + (lane >> 4) * 16 + ks * 32);
            uint32_t qa1 = qa0 + 16 * VSTR;
            uint32_t qh0[4], ql0[4], qh1[4], ql1[4];
            ldmx4(qh0[0], qh0[1], qh0[2], qh0[3], sQh + qa0);
            ldmx4(ql0[0], ql0[1], ql0[2], ql0[3], sQl + qa0);
            ldmx4(qh1[0], qh1[1], qh1[2], qh1[3], sQh + qa1);
            ldmx4(ql1[0], ql1[1], ql1[2], ql1[3], sQl + qa1);
            #pragma unroll
            for (int jp = 0; jp < 2; ++jp) {
                uint32_t kh[4][2], kl[4][2];
                #pragma unroll
                for (int jj = 0; jj < 4; jj += 2) {
                    uint32_t r0, r1, r2, r3;
                    uint32_t a2 = (uint32_t)(((jp * 4 + jj) * 8 + (lane & 15)) * VSTR
                                             + ks * 32 + (lane >> 4) * 16);
                    ldmx4(r0, r1, r2, r3, sKh_ + a2);
                    kh[jj][0] = r0; kh[jj][1] = r2;
                    kh[jj+1][0] = r1; kh[jj+1][1] = r3;
                    ldmx4(r0, r1, r2, r3, sKl_ + a2);
                    kl[jj][0] = r0; kl[jj][1] = r2;
                    kl[jj+1][0] = r1; kl[jj+1][1] = r3;
                }
                #pragma unroll
                for (int jj = 0; jj < 4; ++jj) {
                    int j = jp * 4 + jj;
                    mma16816(Sc0[j], qh0, kh[jj]);
                    mma16816(Sc0[j], qh0, kl[jj]);
                    mma16816(Sc0[j], ql0, kh[jj]);
                    mma16816(Sc1[j], qh1, kh[jj]);
                    mma16816(Sc1[j], qh1, kl[jj]);
                    mma16816(Sc1[j], ql1, kh[jj]);
                }
            }
        }

        // ---- fused exp2 + denominators + P-split, per ks pair ----
        uint32_t pha0[4][4], pla0[4][4], pha1[4][4], pla1[4][4];
        #pragma unroll
        for (int ks = 0; ks < 4; ++ks) {
            float e0, e1, e2, e3;
            e0 = ex2(Sc0[2*ks][0]);   e1 = ex2(Sc0[2*ks][1]);
            e2 = ex2(Sc0[2*ks][2]);   e3 = ex2(Sc0[2*ks][3]);
            l00 += e0 + e1; l01 += e2 + e3;
            split2(e0, e1, pha0[ks][0], pla0[ks][0]);
            split2(e2, e3, pha0[ks][1], pla0[ks][1]);
            e0 = ex2(Sc0[2*ks+1][0]); e1 = ex2(Sc0[2*ks+1][1]);
            e2 = ex2(Sc0[2*ks+1][2]); e3 = ex2(Sc0[2*ks+1][3]);
            l00 += e0 + e1; l01 += e2 + e3;
            split2(e0, e1, pha0[ks][2], pla0[ks][2]);
            split2(e2, e3, pha0[ks][3], pla0[ks][3]);

            e0 = ex2(Sc1[2*ks][0]);   e1 = ex2(Sc1[2*ks][1]);
            e2 = ex2(Sc1[2*ks][2]);   e3 = ex2(Sc1[2*ks][3]);
            l10 += e0 + e1; l11 += e2 + e3;
            split2(e0, e1, pha1[ks][0], pla1[ks][0]);
            split2(e2, e3, pha1[ks][1], pla1[ks][1]);
            e0 = ex2(Sc1[2*ks+1][0]); e1 = ex2(Sc1[2*ks+1][1]);
            e2 = ex2(Sc1[2*ks+1][2]); e3 = ex2(Sc1[2*ks+1][3]);
            l10 += e0 + e1; l11 += e2 + e3;
            split2(e0, e1, pha1[ks][2], pla1[ks][2]);
            split2(e2, e3, pha1[ks][3], pla1[ks][3]);
        }

        // ---- O += P V; V frags loaded once per jd, used by both subs ----
        #pragma unroll
        for (int jd = 0; jd < 8; ++jd) {
            uint32_t vh[4][2], vl[4][2];
            #pragma unroll
            for (int kp = 0; kp < 2; ++kp) {
                uint32_t ao = (uint32_t)((kp * 32 + lane) * VSTR + jd * 16);
                uint32_t r0, r1, r2, r3;
                ldmx4t(r0, r1, r2, r3, sVh_ + ao);
                vh[2*kp][0] = r0; vh[2*kp][1] = r1;
                vh[2*kp+1][0] = r2; vh[2*kp+1][1] = r3;
                ldmx4t(r0, r1, r2, r3, sVl_ + ao);
                vl[2*kp][0] = r0; vl[2*kp][1] = r1;
                vl[2*kp+1][0] = r2; vl[2*kp+1][1] = r3;
            }
            #pragma unroll
            for (int ks = 0; ks < 4; ++ks) {
                mma16816(Oc0[jd], pha0[ks], vh[ks]);
                mma16816(Oc0[jd], pha0[ks], vl[ks]);
                mma16816(Oc0[jd], pla0[ks], vh[ks]);
                mma16816(Oc1[jd], pha1[ks], vh[ks]);
                mma16816(Oc1[jd], pha1[ks], vl[ks]);
                mma16816(Oc1[jd], pla1[ks], vh[ks]);
            }
        }
        __syncthreads();
    }

    // ---- deferred denominator reduction ----
    l00 += __shfl_xor_sync(0xffffffffu, l00, 1);
    l00 += __shfl_xor_sync(0xffffffffu, l00, 2);
    l01 += __shfl_xor_sync(0xffffffffu, l01, 1);
    l01 += __shfl_xor_sync(0xffffffffu, l01, 2);
    l10 += __shfl_xor_sync(0xffffffffu, l10, 1);
    l10 += __shfl_xor_sync(0xffffffffu, l10, 2);
    l11 += __shfl_xor_sync(0xffffffffu, l11, 1);
    l11 += __shfl_xor_sync(0xffffffffu, l11, 2);

    float i00 = 1.0f / l00, i01 = 1.0f / l01;
    float i10 = 1.0f / l10, i11 = 1.0f / l11;
    size_t rg = ((size_t)b * N_ + q0 + wq * 32 + (lane >> 2)) * D_
                + h * 64 + (lane & 3) * 2;
    #pragma unroll
    for (int jd = 0; jd < 8; ++jd) {
        uint32_t uh, ul;
        split2(Oc0[jd][0] * i00, Oc0[jd][1] * i00, uh, ul);
        *(uint32_t*)(Yh + rg + 0 * (size_t)D_ + jd * 8) = uh;
        *(uint32_t*)(Yl + rg + 0 * (size_t)D_ + jd * 8) = ul;
        split2(Oc0[jd][2] * i01, Oc0[jd][3] * i01, uh, ul);
        *(uint32_t*)(Yh + rg + 8 * (size_t)D_ + jd * 8) = uh;
        *(uint32_t*)(Yl + rg + 8 * (size_t)D_ + jd * 8) = ul;
        split2(Oc1[jd][0] * i10, Oc1[jd][1] * i10, uh, ul);
        *(uint32_t*)(Yh + rg + 16 * (size_t)D_ + jd * 8) = uh;
        *(uint32_t*)(Yl + rg + 16 * (size_t)D_ + jd * 8) = ul;
        split2(Oc1[jd][2] * i11, Oc1[jd][3] * i11, uh, ul);
        *(uint32_t*)(Yh + rg + 24 * (size_t)D_ + jd * 8) = uh;
        *(uint32_t*)(Yl + rg + 24 * (size_t)D_ + jd * 8) = ul;
    }
}

// ---------------------------------------------------------------------------
extern "C" void kernel_launch(void* const* d_in, const int* in_sizes, int n_in,
                              void* d_out, int out_size)
{
    const float* x     = (const float*)d_in[0];
    const float* alpha = (const float*)d_in[1];
    const float* bias  = (const float*)d_in[2];
    const float* Wq    = (const float*)d_in[3];
    const float* bq    = (const float*)d_in[4];
    const float* Wk    = (const float*)d_in[5];
    const float* bk    = (const float*)d_in[6];
    const float* Wv    = (const float*)d_in[7];
    const float* bv    = (const float*)d_in[8];
    const float* Wo    = (const float*)d_in[9];
    const float* bo    = (const float*)d_in[10];
    float* out = (float*)d_out;

    __nv_bfloat16 *ahp, *alp, *whp, *wlp, *qhp, *qlp, *khp, *klp, *vhp, *vlp;
    cudaGetSymbolAddress((void**)&ahp, g_Ah);
    cudaGetSymbolAddress((void**)&alp, g_Al);
    cudaGetSymbolAddress((void**)&whp, g_Wh);
    cudaGetSymbolAddress((void**)&wlp, g_Wl);
    cudaGetSymbolAddress((void**)&qhp, g_Qh);
    cudaGetSymbolAddress((void**)&qlp, g_Ql);
    cudaGetSymbolAddress((void**)&khp, g_Kh);
    cudaGetSymbolAddress((void**)&klp, g_Kl);
    cudaGetSymbolAddress((void**)&vhp, g_Vh);
    cudaGetSymbolAddress((void**)&vlp, g_Vl);

    const int gemm_smem = 2 * STAGE_B;                       // 81920
    cudaFuncSetAttribute(gemm_qkv, cudaFuncAttributeMaxDynamicSharedMemorySize,
                         gemm_smem);
    cudaFuncSetAttribute(gemm_out, cudaFuncAttributeMaxDynamicSharedMemorySize,
                         gemm_smem);
    const int attn_smem = 2 * QT * VSTR + 2 * 4 * ATILE;     // 110592
    cudaFuncSetAttribute(attn_mma, cudaFuncAttributeMaxDynamicSharedMemorySize,
                         attn_smem);

    dim3 blk(256);
    prep_kernel<<<dim3(32, 32, 5), blk>>>(x, Wq, Wk, Wv, Wo, whp, wlp, ahp, alp);

    gemm_qkv<<<dim3(8, 32, 3), blk, gemm_smem>>>(
        ahp, alp, whp, wlp, bq, bk, bv, alpha,
        qhp, qlp, khp, klp, vhp, vlp);

    attn_mma<<<dim3(H_, N_ / QT, B_), dim3(ATHR), attn_smem>>>(
        qhp, qlp, khp, klp, vhp, vlp, bias, ahp, alp);

    gemm_out<<<dim3(8, 32), blk, gemm_smem>>>(
        ahp, alp, whp + 3 * (size_t)D_ * D_, wlp + 3 * (size_t)D_ * D_, bo, out);
}